// round 8
// baseline (speedup 1.0000x reference)
#include <cuda_runtime.h>

#define BATCH 32
#define NH    16
#define DK    64
#define DM    1024
#define TC    4096

// Scratch (device globals — no allocation allowed in kernel_launch)
__device__ float g_qp[BATCH * DM];   // scaled query projection
__device__ float g_kp[BATCH * DM];   // new-token key projection
__device__ float g_vp[BATCH * DM];   // new-token value projection
__device__ float g_x [BATCH * DM];   // attention output (pre out-proj)

// ---------------------------------------------------------------------------
// GEMV projection, zero weight replication: grid = (DM/8, nmat), block 128.
// Each warp owns 2 weight rows (register-resident, read from DRAM exactly
// once) and loops over all 32 batches in 4 groups of 8 — 16 independent
// accumulator chains per group hide FMA + shfl latency. act is 128KB total:
// DRAM once, then L1/L2-resident for every other CTA.
// mode 0: QKV — grid.y selects {wq->g_qp (*qscale), wk->g_kp, wv->g_vp}
// mode 1: out-projection — act = g_x (device symbol), W0/B0 -> out_ext
// ---------------------------------------------------------------------------
__global__ void __launch_bounds__(128)
proj_kernel(int mode,
            const float* __restrict__ act_ext,
            const float* __restrict__ W0, const float* __restrict__ B0,
            const float* __restrict__ W1, const float* __restrict__ B1,
            const float* __restrict__ W2, const float* __restrict__ B2,
            float* __restrict__ out_ext,
            float qscale)
{
    const float* act;
    const float* W;
    const float* bias;
    float* out;
    float scale = 1.0f;

    if (mode == 1) {
        act = g_x;  W = W0; bias = B0; out = out_ext;
    } else {
        act = act_ext;
        if (blockIdx.y == 0)      { W = W0; bias = B0; out = g_qp; scale = qscale; }
        else if (blockIdx.y == 1) { W = W1; bias = B1; out = g_kp; }
        else                      { W = W2; bias = B2; out = g_vp; }
    }

    const int warp = threadIdx.x >> 5;
    const int lane = threadIdx.x & 31;
    const int j0   = (blockIdx.x * 4 + warp) * 2;   // 2 rows per warp

    // 2 weight rows register-resident: lane covers k = c*128 + lane*4 .. +3
    float4 w[2][8];
#pragma unroll
    for (int r = 0; r < 2; r++) {
        const float* Wr = W + (size_t)(j0 + r) * DM;
#pragma unroll
        for (int c = 0; c < 8; c++)
            w[r][c] = *(const float4*)(Wr + c * 128 + lane * 4);
    }

    const float bias0 = bias[j0], bias1 = bias[j0 + 1];

    // All 32 batches: 4 groups of 8 (16 interleaved acc chains per group)
#pragma unroll
    for (int g = 0; g < 4; g++) {
        const int b0 = g * 8;
        float a[8][2];
#pragma unroll
        for (int bb = 0; bb < 8; bb++) { a[bb][0] = 0.0f; a[bb][1] = 0.0f; }

#pragma unroll
        for (int c = 0; c < 8; c++) {
#pragma unroll
            for (int bb = 0; bb < 8; bb++) {
                float4 x = *(const float4*)(act + (size_t)(b0 + bb) * DM
                                            + c * 128 + lane * 4);
                a[bb][0] += x.x * w[0][c].x + x.y * w[0][c].y
                          + x.z * w[0][c].z + x.w * w[0][c].w;
                a[bb][1] += x.x * w[1][c].x + x.y * w[1][c].y
                          + x.z * w[1][c].z + x.w * w[1][c].w;
            }
        }

#pragma unroll
        for (int off = 16; off; off >>= 1) {
#pragma unroll
            for (int bb = 0; bb < 8; bb++) {
                a[bb][0] += __shfl_xor_sync(0xffffffffu, a[bb][0], off);
                a[bb][1] += __shfl_xor_sync(0xffffffffu, a[bb][1], off);
            }
        }

        if (lane == 0) {
#pragma unroll
            for (int bb = 0; bb < 8; bb++) {
                out[(size_t)(b0 + bb) * DM + j0]     = (a[bb][0] + bias0) * scale;
                out[(size_t)(b0 + bb) * DM + j0 + 1] = (a[bb][1] + bias1) * scale;
            }
        }
    }
}

// ---------------------------------------------------------------------------
// Flash-decode attention over 4096 cached keys + 1 new token (R7-proven,
// at HBM roofline: ~7.2 TB/s — unchanged).
// One CTA per (b,h): 512 CTAs x 256 threads, single wave (4 CTAs/SM).
// float4 / half-warp layout; block-softmax over 4-key blocks per half.
// ---------------------------------------------------------------------------
__global__ void __launch_bounds__(256, 4)
attn_kernel(const float* __restrict__ Kc,
            const float* __restrict__ Vc)
{
    const int bh   = blockIdx.x;       // 0..511
    const int b    = bh >> 4;
    const int h    = bh & 15;
    const int warp = threadIdx.x >> 5;
    const int lane = threadIdx.x & 31;
    const int half = lane >> 4;        // 0 or 1
    const int li   = lane & 15;        // lane within half; dims 4*li..4*li+3

    __shared__ float4 sq[16];          // q, pre-scaled by 1/sqrt(DK)
    __shared__ float  sm[16], sl[16];
    __shared__ float4 so[16][16];

    if (threadIdx.x < 16)
        sq[threadIdx.x] = *(const float4*)(g_qp + b * DM + h * DK + 4 * threadIdx.x);
    __syncthreads();

    const float4 q4 = sq[li];

    const float* Kp = Kc + (size_t)bh * TC * DK + (size_t)half * DK + 4 * li;
    const float* Vp = Vc + (size_t)bh * TC * DK + (size_t)half * DK + 4 * li;

    float  m = -1e30f;
    float  l = 0.0f;
    float4 o = make_float4(0.f, 0.f, 0.f, 0.f);

    const int t0 = warp * (TC / 8);    // 512 keys per warp; 4/half per iter
    for (int t = t0; t < t0 + TC / 8; t += 8) {
        float4 kk[4], vv[4];
#pragma unroll
        for (int i = 0; i < 4; i++)
            kk[i] = __ldcs((const float4*)(Kp + (size_t)(t + 2 * i) * DK));
#pragma unroll
        for (int i = 0; i < 4; i++)
            vv[i] = __ldcs((const float4*)(Vp + (size_t)(t + 2 * i) * DK));

        float s[4];
#pragma unroll
        for (int i = 0; i < 4; i++)
            s[i] = kk[i].x * q4.x + kk[i].y * q4.y + kk[i].z * q4.z + kk[i].w * q4.w;
#pragma unroll
        for (int off = 8; off; off >>= 1)
#pragma unroll
            for (int i = 0; i < 4; i++)
                s[i] += __shfl_xor_sync(0xffffffffu, s[i], off);   // within half

        float bm = fmaxf(fmaxf(s[0], s[1]), fmaxf(s[2], s[3]));
        float mn = fmaxf(m, bm);

        float p[4];
#pragma unroll
        for (int i = 0; i < 4; i++) p[i] = __expf(s[i] - mn);

        float  lp = 0.0f;
        float4 op = make_float4(0.f, 0.f, 0.f, 0.f);
#pragma unroll
        for (int i = 0; i < 4; i++) {
            lp   += p[i];
            op.x += p[i] * vv[i].x;
            op.y += p[i] * vv[i].y;
            op.z += p[i] * vv[i].z;
            op.w += p[i] * vv[i].w;
        }

        float sc = __expf(m - mn);
        l   = l   * sc + lp;
        o.x = o.x * sc + op.x;
        o.y = o.y * sc + op.y;
        o.z = o.z * sc + op.z;
        o.w = o.w * sc + op.w;
        m   = mn;
    }

    // New (appended) token: warp 0 computes the score; half 0 folds it in.
    if (warp == 0) {
        float4 kk = *(const float4*)(g_kp + b * DM + h * DK + 4 * li);
        float4 vv = *(const float4*)(g_vp + b * DM + h * DK + 4 * li);
        float s = kk.x * q4.x + kk.y * q4.y + kk.z * q4.z + kk.w * q4.w;
#pragma unroll
        for (int off = 8; off; off >>= 1)
            s += __shfl_xor_sync(0xffffffffu, s, off);
        if (half == 0) {
            float mn = fmaxf(m, s);
            float sc = __expf(m - mn);
            float p  = __expf(s - mn);
            l   = l   * sc + p;
            o.x = o.x * sc + p * vv.x;
            o.y = o.y * sc + p * vv.y;
            o.z = o.z * sc + p * vv.z;
            o.w = o.w * sc + p * vv.w;
            m   = mn;
        }
    }

    const int idx = warp * 2 + half;   // 16 partial states
    if (li == 0) { sm[idx] = m; sl[idx] = l; }
    so[idx][li] = o;
    __syncthreads();

    // Combine 16 partial states; threads 0..63 each own one output dim.
    if (threadIdx.x < DK) {
        const int d = threadIdx.x;
        float M = sm[0];
#pragma unroll
        for (int i = 1; i < 16; i++) M = fmaxf(M, sm[i]);
        float L = 0.0f, O = 0.0f;
#pragma unroll
        for (int i = 0; i < 16; i++) {
            float e = __expf(sm[i] - M);
            L += e * sl[i];
            O += e * ((const float*)so[i])[d];
        }
        g_x[b * DM + h * DK + d] = O / L;
    }
}

// ---------------------------------------------------------------------------
// inputs (metadata order): 0 q, 1 key_pre, 2 value_pre,
//   3 wq, 4 bq, 5 wk, 6 bk, 7 wv, 8 bv, 9 wo, 10 bo
// output: [32, 1, 1024] fp32
// ---------------------------------------------------------------------------
extern "C" void kernel_launch(void* const* d_in, const int* in_sizes, int n_in,
                              void* d_out, int out_size)
{
    const float* q   = (const float*)d_in[0];
    const float* Kc  = (const float*)d_in[1];
    const float* Vc  = (const float*)d_in[2];
    const float* wq  = (const float*)d_in[3];
    const float* bq  = (const float*)d_in[4];
    const float* wk  = (const float*)d_in[5];
    const float* bk  = (const float*)d_in[6];
    const float* wv  = (const float*)d_in[7];
    const float* bv  = (const float*)d_in[8];
    const float* wo  = (const float*)d_in[9];
    const float* bo  = (const float*)d_in[10];
    float* out = (float*)d_out;

    const float qscale = 0.125f;  // 1/sqrt(DK)

    // QKV projections (grid.y selects matrix; weights read from DRAM once)
    proj_kernel<<<dim3(DM / 8, 3), 128>>>(0, q, wq, bq, wk, bk, wv, bv,
                                          nullptr, qscale);

    // Flash-decode attention over the cache + appended token (single wave)
    attn_kernel<<<BATCH * NH, 256>>>(Kc, Vc);

    // Output projection: reads g_x via device-side symbol, writes d_out
    proj_kernel<<<dim3(DM / 8, 1), 128>>>(1, nullptr, wo, bo, nullptr, nullptr,
                                          nullptr, nullptr, out, 1.0f);
}

// round 9
// speedup vs baseline: 1.0358x; 1.0358x over previous
#include <cuda_runtime.h>
#include <cstdint>

#define BATCH 32
#define NH    16
#define DK    64
#define DM    1024
#define TC    4096

// Scratch (device globals — no allocation allowed in kernel_launch)
__device__ float g_qp[BATCH * DM];   // scaled query projection
__device__ float g_kp[BATCH * DM];   // new-token key projection
__device__ float g_vp[BATCH * DM];   // new-token value projection
__device__ float g_x [BATCH * DM];   // attention output (pre out-proj)

// ---------------------------------------------------------------------------
// GEMV projection with smem-staged activations.
// grid = (DM/8, nmat, 8), block 128: CTA owns 8 rows x 4 batches (R7 shape).
// The CTA's 16KB act slice is staged into smem with cp.async (register-free,
// all 1024 lines in flight) while the 16 weight LDG.128/warp stream from
// DRAM. Compute reads act via LDS — no per-use L2 latency exposure, which
// was the measured limiter (both R7/R8 configs stuck at ~600 GB/s).
// mode 0: QKV — grid.y selects {wq->g_qp (*qscale), wk->g_kp, wv->g_vp}
// mode 1: out-projection — act = g_x (device symbol), W0/B0 -> out_ext
// ---------------------------------------------------------------------------
__global__ void __launch_bounds__(128)
proj_kernel(int mode,
            const float* __restrict__ act_ext,
            const float* __restrict__ W0, const float* __restrict__ B0,
            const float* __restrict__ W1, const float* __restrict__ B1,
            const float* __restrict__ W2, const float* __restrict__ B2,
            float* __restrict__ out_ext,
            float qscale)
{
    const float* act;
    const float* W;
    const float* bias;
    float* out;
    float scale = 1.0f;

    if (mode == 1) {
        act = g_x;  W = W0; bias = B0; out = out_ext;
    } else {
        act = act_ext;
        if (blockIdx.y == 0)      { W = W0; bias = B0; out = g_qp; scale = qscale; }
        else if (blockIdx.y == 1) { W = W1; bias = B1; out = g_kp; }
        else                      { W = W2; bias = B2; out = g_vp; }
    }

    const int warp = threadIdx.x >> 5;
    const int lane = threadIdx.x & 31;
    const int j0   = (blockIdx.x * 4 + warp) * 2;   // 2 rows per warp
    const int b0   = blockIdx.z * 4;                // 4 batches per z-slice

    __shared__ __align__(16) float s_act[4 * DM];   // 16 KB act slice

    // Stage act into smem: 1024 x 16B lines, 8 per thread, register-free.
    {
        const float* src = act + (size_t)b0 * DM;
        uint32_t sbase = (uint32_t)__cvta_generic_to_shared(s_act);
#pragma unroll
        for (int i = 0; i < 8; i++) {
            int u = i * 128 + threadIdx.x;          // 16B unit index
            asm volatile("cp.async.cg.shared.global [%0], [%1], 16;"
                         :: "r"(sbase + u * 16), "l"(src + u * 4) : "memory");
        }
        asm volatile("cp.async.commit_group;" ::: "memory");
    }

    // Weight rows into registers (overlaps the async copy).
    float4 w[2][8];
#pragma unroll
    for (int r = 0; r < 2; r++) {
        const float* Wr = W + (size_t)(j0 + r) * DM;
#pragma unroll
        for (int c = 0; c < 8; c++)
            w[r][c] = *(const float4*)(Wr + c * 128 + lane * 4);
    }

    asm volatile("cp.async.wait_group 0;" ::: "memory");
    __syncthreads();

    // 8 interleaved accumulator chains (4 batches x 2 rows), act via LDS.
    float a[4][2];
#pragma unroll
    for (int b = 0; b < 4; b++) { a[b][0] = 0.0f; a[b][1] = 0.0f; }

#pragma unroll
    for (int c = 0; c < 8; c++) {
#pragma unroll
        for (int b = 0; b < 4; b++) {
            float4 x = *(const float4*)&s_act[b * DM + c * 128 + lane * 4];
            a[b][0] += x.x * w[0][c].x + x.y * w[0][c].y
                     + x.z * w[0][c].z + x.w * w[0][c].w;
            a[b][1] += x.x * w[1][c].x + x.y * w[1][c].y
                     + x.z * w[1][c].z + x.w * w[1][c].w;
        }
    }

#pragma unroll
    for (int off = 16; off; off >>= 1) {
#pragma unroll
        for (int b = 0; b < 4; b++) {
            a[b][0] += __shfl_xor_sync(0xffffffffu, a[b][0], off);
            a[b][1] += __shfl_xor_sync(0xffffffffu, a[b][1], off);
        }
    }

    if (lane == 0) {
        const float bias0 = bias[j0], bias1 = bias[j0 + 1];
#pragma unroll
        for (int b = 0; b < 4; b++) {
            out[(size_t)(b0 + b) * DM + j0]     = (a[b][0] + bias0) * scale;
            out[(size_t)(b0 + b) * DM + j0 + 1] = (a[b][1] + bias1) * scale;
        }
    }
}

// ---------------------------------------------------------------------------
// Flash-decode attention over 4096 cached keys + 1 new token (R7-proven,
// at HBM roofline ~7.2 TB/s — UNCHANGED).
// One CTA per (b,h): 512 CTAs x 256 threads, single wave (4 CTAs/SM).
// float4 / half-warp layout; block-softmax over 4-key blocks per half.
// ---------------------------------------------------------------------------
__global__ void __launch_bounds__(256, 4)
attn_kernel(const float* __restrict__ Kc,
            const float* __restrict__ Vc)
{
    const int bh   = blockIdx.x;       // 0..511
    const int b    = bh >> 4;
    const int h    = bh & 15;
    const int warp = threadIdx.x >> 5;
    const int lane = threadIdx.x & 31;
    const int half = lane >> 4;        // 0 or 1
    const int li   = lane & 15;        // lane within half; dims 4*li..4*li+3

    __shared__ float4 sq[16];          // q, pre-scaled by 1/sqrt(DK)
    __shared__ float  sm[16], sl[16];
    __shared__ float4 so[16][16];

    if (threadIdx.x < 16)
        sq[threadIdx.x] = *(const float4*)(g_qp + b * DM + h * DK + 4 * threadIdx.x);
    __syncthreads();

    const float4 q4 = sq[li];

    const float* Kp = Kc + (size_t)bh * TC * DK + (size_t)half * DK + 4 * li;
    const float* Vp = Vc + (size_t)bh * TC * DK + (size_t)half * DK + 4 * li;

    float  m = -1e30f;
    float  l = 0.0f;
    float4 o = make_float4(0.f, 0.f, 0.f, 0.f);

    const int t0 = warp * (TC / 8);    // 512 keys per warp; 4/half per iter
    for (int t = t0; t < t0 + TC / 8; t += 8) {
        float4 kk[4], vv[4];
#pragma unroll
        for (int i = 0; i < 4; i++)
            kk[i] = __ldcs((const float4*)(Kp + (size_t)(t + 2 * i) * DK));
#pragma unroll
        for (int i = 0; i < 4; i++)
            vv[i] = __ldcs((const float4*)(Vp + (size_t)(t + 2 * i) * DK));

        float s[4];
#pragma unroll
        for (int i = 0; i < 4; i++)
            s[i] = kk[i].x * q4.x + kk[i].y * q4.y + kk[i].z * q4.z + kk[i].w * q4.w;
#pragma unroll
        for (int off = 8; off; off >>= 1)
#pragma unroll
            for (int i = 0; i < 4; i++)
                s[i] += __shfl_xor_sync(0xffffffffu, s[i], off);   // within half

        float bm = fmaxf(fmaxf(s[0], s[1]), fmaxf(s[2], s[3]));
        float mn = fmaxf(m, bm);

        float p[4];
#pragma unroll
        for (int i = 0; i < 4; i++) p[i] = __expf(s[i] - mn);

        float  lp = 0.0f;
        float4 op = make_float4(0.f, 0.f, 0.f, 0.f);
#pragma unroll
        for (int i = 0; i < 4; i++) {
            lp   += p[i];
            op.x += p[i] * vv[i].x;
            op.y += p[i] * vv[i].y;
            op.z += p[i] * vv[i].z;
            op.w += p[i] * vv[i].w;
        }

        float sc = __expf(m - mn);
        l   = l   * sc + lp;
        o.x = o.x * sc + op.x;
        o.y = o.y * sc + op.y;
        o.z = o.z * sc + op.z;
        o.w = o.w * sc + op.w;
        m   = mn;
    }

    // New (appended) token: warp 0 computes the score; half 0 folds it in.
    if (warp == 0) {
        float4 kk = *(const float4*)(g_kp + b * DM + h * DK + 4 * li);
        float4 vv = *(const float4*)(g_vp + b * DM + h * DK + 4 * li);
        float s = kk.x * q4.x + kk.y * q4.y + kk.z * q4.z + kk.w * q4.w;
#pragma unroll
        for (int off = 8; off; off >>= 1)
            s += __shfl_xor_sync(0xffffffffu, s, off);
        if (half == 0) {
            float mn = fmaxf(m, s);
            float sc = __expf(m - mn);
            float p  = __expf(s - mn);
            l   = l   * sc + p;
            o.x = o.x * sc + p * vv.x;
            o.y = o.y * sc + p * vv.y;
            o.z = o.z * sc + p * vv.z;
            o.w = o.w * sc + p * vv.w;
            m   = mn;
        }
    }

    const int idx = warp * 2 + half;   // 16 partial states
    if (li == 0) { sm[idx] = m; sl[idx] = l; }
    so[idx][li] = o;
    __syncthreads();

    // Combine 16 partial states; threads 0..63 each own one output dim.
    if (threadIdx.x < DK) {
        const int d = threadIdx.x;
        float M = sm[0];
#pragma unroll
        for (int i = 1; i < 16; i++) M = fmaxf(M, sm[i]);
        float L = 0.0f, O = 0.0f;
#pragma unroll
        for (int i = 0; i < 16; i++) {
            float e = __expf(sm[i] - M);
            L += e * sl[i];
            O += e * ((const float*)so[i])[d];
        }
        g_x[b * DM + h * DK + d] = O / L;
    }
}

// ---------------------------------------------------------------------------
// inputs (metadata order): 0 q, 1 key_pre, 2 value_pre,
//   3 wq, 4 bq, 5 wk, 6 bk, 7 wv, 8 bv, 9 wo, 10 bo
// output: [32, 1, 1024] fp32
// ---------------------------------------------------------------------------
extern "C" void kernel_launch(void* const* d_in, const int* in_sizes, int n_in,
                              void* d_out, int out_size)
{
    const float* q   = (const float*)d_in[0];
    const float* Kc  = (const float*)d_in[1];
    const float* Vc  = (const float*)d_in[2];
    const float* wq  = (const float*)d_in[3];
    const float* bq  = (const float*)d_in[4];
    const float* wk  = (const float*)d_in[5];
    const float* bk  = (const float*)d_in[6];
    const float* wv  = (const float*)d_in[7];
    const float* bv  = (const float*)d_in[8];
    const float* wo  = (const float*)d_in[9];
    const float* bo  = (const float*)d_in[10];
    float* out = (float*)d_out;

    const float qscale = 0.125f;  // 1/sqrt(DK)

    // QKV projections (grid.y selects matrix; q gets the softmax scale folded in)
    proj_kernel<<<dim3(DM / 8, 3, 8), 128>>>(0, q, wq, bq, wk, bk, wv, bv,
                                             nullptr, qscale);

    // Flash-decode attention over the cache + appended token (single wave)
    attn_kernel<<<BATCH * NH, 256>>>(Kc, Vc);

    // Output projection: reads g_x via device-side symbol, writes d_out
    proj_kernel<<<dim3(DM / 8, 1, 8), 128>>>(1, nullptr, wo, bo, nullptr, nullptr,
                                             nullptr, nullptr, out, 1.0f);
}

// round 10
// speedup vs baseline: 1.0399x; 1.0040x over previous
#include <cuda_runtime.h>
#include <cstdint>

#define BATCH 32
#define NH    16
#define DK    64
#define DM    1024
#define TC    4096

// Scratch (device globals — no allocation allowed in kernel_launch)
__device__ float g_qp[BATCH * DM];   // scaled query projection
__device__ float g_kp[BATCH * DM];   // new-token key projection
__device__ float g_vp[BATCH * DM];   // new-token value projection
__device__ float g_x [BATCH * DM];   // attention output (pre out-proj)

// ---------------------------------------------------------------------------
// GEMV projection, double-buffered act staging.
// grid = (DM/8, nmat, 4), block 128: CTA owns 8 rows x 8 batches, processed
// as two cp.async-staged groups of 4 batches. Both copies are committed up
// front; weight LDGs overlap copy0's latency, compute on group 0 overlaps
// copy1's arrival — breaks the wave-synchronized stall (issue=44% in R9).
// z=4 also halves weight L2 replication (96MB -> 48MB).
// mode 0: QKV — grid.y selects {wq->g_qp (*qscale), wk->g_kp, wv->g_vp}
// mode 1: out-projection — act = g_x (device symbol), W0/B0 -> out_ext
// ---------------------------------------------------------------------------
__global__ void __launch_bounds__(128)
proj_kernel(int mode,
            const float* __restrict__ act_ext,
            const float* __restrict__ W0, const float* __restrict__ B0,
            const float* __restrict__ W1, const float* __restrict__ B1,
            const float* __restrict__ W2, const float* __restrict__ B2,
            float* __restrict__ out_ext,
            float qscale)
{
    const float* act;
    const float* W;
    const float* bias;
    float* out;
    float scale = 1.0f;

    if (mode == 1) {
        act = g_x;  W = W0; bias = B0; out = out_ext;
    } else {
        act = act_ext;
        if (blockIdx.y == 0)      { W = W0; bias = B0; out = g_qp; scale = qscale; }
        else if (blockIdx.y == 1) { W = W1; bias = B1; out = g_kp; }
        else                      { W = W2; bias = B2; out = g_vp; }
    }

    const int warp = threadIdx.x >> 5;
    const int lane = threadIdx.x & 31;
    const int j0   = (blockIdx.x * 4 + warp) * 2;   // 2 rows per warp
    const int b0   = blockIdx.z * 8;                // 8 batches per z-slice

    __shared__ __align__(16) float s_act[2][4 * DM];   // 2 x 16 KB act groups

    // Stage both 4-batch act groups (register-free LDGSTS, all in flight).
    {
        const float* src0 = act + (size_t)b0 * DM;
        const float* src1 = act + (size_t)(b0 + 4) * DM;
        uint32_t sb0 = (uint32_t)__cvta_generic_to_shared(s_act[0]);
        uint32_t sb1 = (uint32_t)__cvta_generic_to_shared(s_act[1]);
#pragma unroll
        for (int i = 0; i < 8; i++) {
            int u = i * 128 + threadIdx.x;          // 16B unit index, 1024 total
            asm volatile("cp.async.cg.shared.global [%0], [%1], 16;"
                         :: "r"(sb0 + u * 16), "l"(src0 + u * 4) : "memory");
        }
        asm volatile("cp.async.commit_group;" ::: "memory");
#pragma unroll
        for (int i = 0; i < 8; i++) {
            int u = i * 128 + threadIdx.x;
            asm volatile("cp.async.cg.shared.global [%0], [%1], 16;"
                         :: "r"(sb1 + u * 16), "l"(src1 + u * 4) : "memory");
        }
        asm volatile("cp.async.commit_group;" ::: "memory");
    }

    // Weight rows into registers (latency overlaps the copies).
    float4 w[2][8];
#pragma unroll
    for (int r = 0; r < 2; r++) {
        const float* Wr = W + (size_t)(j0 + r) * DM;
#pragma unroll
        for (int c = 0; c < 8; c++)
            w[r][c] = *(const float4*)(Wr + c * 128 + lane * 4);
    }
    const float bias0 = bias[j0], bias1 = bias[j0 + 1];

    // ---- group 0: wait only for the first copy group ----
    asm volatile("cp.async.wait_group 1;" ::: "memory");
    __syncthreads();

#pragma unroll
    for (int g = 0; g < 2; g++) {
        const float* sa = s_act[g];
        float a[4][2];
#pragma unroll
        for (int b = 0; b < 4; b++) { a[b][0] = 0.0f; a[b][1] = 0.0f; }

#pragma unroll
        for (int c = 0; c < 8; c++) {
#pragma unroll
            for (int b = 0; b < 4; b++) {
                float4 x = *(const float4*)&sa[b * DM + c * 128 + lane * 4];
                a[b][0] += x.x * w[0][c].x + x.y * w[0][c].y
                         + x.z * w[0][c].z + x.w * w[0][c].w;
                a[b][1] += x.x * w[1][c].x + x.y * w[1][c].y
                         + x.z * w[1][c].z + x.w * w[1][c].w;
            }
        }

#pragma unroll
        for (int off = 16; off; off >>= 1) {
#pragma unroll
            for (int b = 0; b < 4; b++) {
                a[b][0] += __shfl_xor_sync(0xffffffffu, a[b][0], off);
                a[b][1] += __shfl_xor_sync(0xffffffffu, a[b][1], off);
            }
        }

        if (lane == 0) {
            const int bb0 = b0 + g * 4;
#pragma unroll
            for (int b = 0; b < 4; b++) {
                out[(size_t)(bb0 + b) * DM + j0]     = (a[b][0] + bias0) * scale;
                out[(size_t)(bb0 + b) * DM + j0 + 1] = (a[b][1] + bias1) * scale;
            }
        }

        if (g == 0) {   // ---- group 1 arrival ----
            asm volatile("cp.async.wait_group 0;" ::: "memory");
            __syncthreads();
        }
    }
}

// ---------------------------------------------------------------------------
// Flash-decode attention over 4096 cached keys + 1 new token (R7-proven,
// at HBM roofline ~7.2 TB/s — UNCHANGED).
// One CTA per (b,h): 512 CTAs x 256 threads, single wave (4 CTAs/SM).
// float4 / half-warp layout; block-softmax over 4-key blocks per half.
// ---------------------------------------------------------------------------
__global__ void __launch_bounds__(256, 4)
attn_kernel(const float* __restrict__ Kc,
            const float* __restrict__ Vc)
{
    const int bh   = blockIdx.x;       // 0..511
    const int b    = bh >> 4;
    const int h    = bh & 15;
    const int warp = threadIdx.x >> 5;
    const int lane = threadIdx.x & 31;
    const int half = lane >> 4;        // 0 or 1
    const int li   = lane & 15;        // lane within half; dims 4*li..4*li+3

    __shared__ float4 sq[16];          // q, pre-scaled by 1/sqrt(DK)
    __shared__ float  sm[16], sl[16];
    __shared__ float4 so[16][16];

    if (threadIdx.x < 16)
        sq[threadIdx.x] = *(const float4*)(g_qp + b * DM + h * DK + 4 * threadIdx.x);
    __syncthreads();

    const float4 q4 = sq[li];

    const float* Kp = Kc + (size_t)bh * TC * DK + (size_t)half * DK + 4 * li;
    const float* Vp = Vc + (size_t)bh * TC * DK + (size_t)half * DK + 4 * li;

    float  m = -1e30f;
    float  l = 0.0f;
    float4 o = make_float4(0.f, 0.f, 0.f, 0.f);

    const int t0 = warp * (TC / 8);    // 512 keys per warp; 4/half per iter
    for (int t = t0; t < t0 + TC / 8; t += 8) {
        float4 kk[4], vv[4];
#pragma unroll
        for (int i = 0; i < 4; i++)
            kk[i] = __ldcs((const float4*)(Kp + (size_t)(t + 2 * i) * DK));
#pragma unroll
        for (int i = 0; i < 4; i++)
            vv[i] = __ldcs((const float4*)(Vp + (size_t)(t + 2 * i) * DK));

        float s[4];
#pragma unroll
        for (int i = 0; i < 4; i++)
            s[i] = kk[i].x * q4.x + kk[i].y * q4.y + kk[i].z * q4.z + kk[i].w * q4.w;
#pragma unroll
        for (int off = 8; off; off >>= 1)
#pragma unroll
            for (int i = 0; i < 4; i++)
                s[i] += __shfl_xor_sync(0xffffffffu, s[i], off);   // within half

        float bm = fmaxf(fmaxf(s[0], s[1]), fmaxf(s[2], s[3]));
        float mn = fmaxf(m, bm);

        float p[4];
#pragma unroll
        for (int i = 0; i < 4; i++) p[i] = __expf(s[i] - mn);

        float  lp = 0.0f;
        float4 op = make_float4(0.f, 0.f, 0.f, 0.f);
#pragma unroll
        for (int i = 0; i < 4; i++) {
            lp   += p[i];
            op.x += p[i] * vv[i].x;
            op.y += p[i] * vv[i].y;
            op.z += p[i] * vv[i].z;
            op.w += p[i] * vv[i].w;
        }

        float sc = __expf(m - mn);
        l   = l   * sc + lp;
        o.x = o.x * sc + op.x;
        o.y = o.y * sc + op.y;
        o.z = o.z * sc + op.z;
        o.w = o.w * sc + op.w;
        m   = mn;
    }

    // New (appended) token: warp 0 computes the score; half 0 folds it in.
    if (warp == 0) {
        float4 kk = *(const float4*)(g_kp + b * DM + h * DK + 4 * li);
        float4 vv = *(const float4*)(g_vp + b * DM + h * DK + 4 * li);
        float s = kk.x * q4.x + kk.y * q4.y + kk.z * q4.z + kk.w * q4.w;
#pragma unroll
        for (int off = 8; off; off >>= 1)
            s += __shfl_xor_sync(0xffffffffu, s, off);
        if (half == 0) {
            float mn = fmaxf(m, s);
            float sc = __expf(m - mn);
            float p  = __expf(s - mn);
            l   = l   * sc + p;
            o.x = o.x * sc + p * vv.x;
            o.y = o.y * sc + p * vv.y;
            o.z = o.z * sc + p * vv.z;
            o.w = o.w * sc + p * vv.w;
            m   = mn;
        }
    }

    const int idx = warp * 2 + half;   // 16 partial states
    if (li == 0) { sm[idx] = m; sl[idx] = l; }
    so[idx][li] = o;
    __syncthreads();

    // Combine 16 partial states; threads 0..63 each own one output dim.
    if (threadIdx.x < DK) {
        const int d = threadIdx.x;
        float M = sm[0];
#pragma unroll
        for (int i = 1; i < 16; i++) M = fmaxf(M, sm[i]);
        float L = 0.0f, O = 0.0f;
#pragma unroll
        for (int i = 0; i < 16; i++) {
            float e = __expf(sm[i] - M);
            L += e * sl[i];
            O += e * ((const float*)so[i])[d];
        }
        g_x[b * DM + h * DK + d] = O / L;
    }
}

// ---------------------------------------------------------------------------
// inputs (metadata order): 0 q, 1 key_pre, 2 value_pre,
//   3 wq, 4 bq, 5 wk, 6 bk, 7 wv, 8 bv, 9 wo, 10 bo
// output: [32, 1, 1024] fp32
// ---------------------------------------------------------------------------
extern "C" void kernel_launch(void* const* d_in, const int* in_sizes, int n_in,
                              void* d_out, int out_size)
{
    const float* q   = (const float*)d_in[0];
    const float* Kc  = (const float*)d_in[1];
    const float* Vc  = (const float*)d_in[2];
    const float* wq  = (const float*)d_in[3];
    const float* bq  = (const float*)d_in[4];
    const float* wk  = (const float*)d_in[5];
    const float* bk  = (const float*)d_in[6];
    const float* wv  = (const float*)d_in[7];
    const float* bv  = (const float*)d_in[8];
    const float* wo  = (const float*)d_in[9];
    const float* bo  = (const float*)d_in[10];
    float* out = (float*)d_out;

    const float qscale = 0.125f;  // 1/sqrt(DK)

    // QKV projections (grid.y selects matrix; q gets the softmax scale folded in)
    proj_kernel<<<dim3(DM / 8, 3, 4), 128>>>(0, q, wq, bq, wk, bk, wv, bv,
                                             nullptr, qscale);

    // Flash-decode attention over the cache + appended token (single wave)
    attn_kernel<<<BATCH * NH, 256>>>(Kc, Vc);

    // Output projection: reads g_x via device-side symbol, writes d_out
    proj_kernel<<<dim3(DM / 8, 1, 4), 128>>>(1, nullptr, wo, bo, nullptr, nullptr,
                                             nullptr, nullptr, out, 1.0f);
}

// round 11
// speedup vs baseline: 1.0433x; 1.0032x over previous
#include <cuda_runtime.h>
#include <cstdint>

#define BATCH 32
#define NH    16
#define DK    64
#define DM    1024
#define TC    4096

// Scratch (device globals — no allocation allowed in kernel_launch)
__device__ float g_qp[BATCH * DM];   // scaled query projection
__device__ float g_kp[BATCH * DM];   // new-token key projection
__device__ float g_vp[BATCH * DM];   // new-token value projection
__device__ float g_x [BATCH * DM];   // attention output (pre out-proj)

// Packed dual-FMA: d.(lo,hi) += a.(lo,hi) * b.(lo,hi)   (sm_103a FFMA2, rt=2
// for TWO fp32 FMAs — ptxas never emits it from scalar C++; PTX-only.)
__device__ __forceinline__ void ffma2(unsigned long long& d,
                                      unsigned long long a,
                                      unsigned long long b)
{
    asm("fma.rn.f32x2 %0, %1, %2, %0;" : "+l"(d) : "l"(a), "l"(b));
}

__device__ __forceinline__ float pair_sum(unsigned long long v)
{
    return __uint_as_float((unsigned)v) + __uint_as_float((unsigned)(v >> 32));
}

// ---------------------------------------------------------------------------
// GEMV projection, double-buffered act staging + packed f32x2 FMAs.
// grid = (DM/8, nmat, 4), block 128: CTA owns 8 rows x 8 batches, processed
// as two cp.async-staged groups of 4 batches (copies committed up front;
// weight LDGs overlap copy0, compute on group 0 overlaps copy1's arrival).
// Inner product uses fma.rn.f32x2 on (even-k, odd-k) pairs — HALF the FFMA
// instruction count, beating the sm_103a half-rate 3-reg FFMA issue floor
// that pinned this kernel at ~16us / 43% issue across R7-R10.
// mode 0: QKV — grid.y selects {wq->g_qp (*qscale), wk->g_kp, wv->g_vp}
// mode 1: out-projection — act = g_x (device symbol), W0/B0 -> out_ext
// ---------------------------------------------------------------------------
__global__ void __launch_bounds__(128)
proj_kernel(int mode,
            const float* __restrict__ act_ext,
            const float* __restrict__ W0, const float* __restrict__ B0,
            const float* __restrict__ W1, const float* __restrict__ B1,
            const float* __restrict__ W2, const float* __restrict__ B2,
            float* __restrict__ out_ext,
            float qscale)
{
    const float* act;
    const float* W;
    const float* bias;
    float* out;
    float scale = 1.0f;

    if (mode == 1) {
        act = g_x;  W = W0; bias = B0; out = out_ext;
    } else {
        act = act_ext;
        if (blockIdx.y == 0)      { W = W0; bias = B0; out = g_qp; scale = qscale; }
        else if (blockIdx.y == 1) { W = W1; bias = B1; out = g_kp; }
        else                      { W = W2; bias = B2; out = g_vp; }
    }

    const int warp = threadIdx.x >> 5;
    const int lane = threadIdx.x & 31;
    const int j0   = (blockIdx.x * 4 + warp) * 2;   // 2 rows per warp
    const int b0   = blockIdx.z * 8;                // 8 batches per z-slice

    __shared__ __align__(16) float s_act[2][4 * DM];   // 2 x 16 KB act groups

    // Stage both 4-batch act groups (register-free LDGSTS, all in flight).
    {
        const float* src0 = act + (size_t)b0 * DM;
        const float* src1 = act + (size_t)(b0 + 4) * DM;
        uint32_t sb0 = (uint32_t)__cvta_generic_to_shared(s_act[0]);
        uint32_t sb1 = (uint32_t)__cvta_generic_to_shared(s_act[1]);
#pragma unroll
        for (int i = 0; i < 8; i++) {
            int u = i * 128 + threadIdx.x;          // 16B unit index, 1024 total
            asm volatile("cp.async.cg.shared.global [%0], [%1], 16;"
                         :: "r"(sb0 + u * 16), "l"(src0 + u * 4) : "memory");
        }
        asm volatile("cp.async.commit_group;" ::: "memory");
#pragma unroll
        for (int i = 0; i < 8; i++) {
            int u = i * 128 + threadIdx.x;
            asm volatile("cp.async.cg.shared.global [%0], [%1], 16;"
                         :: "r"(sb1 + u * 16), "l"(src1 + u * 4) : "memory");
        }
        asm volatile("cp.async.commit_group;" ::: "memory");
    }

    // Weight rows into registers as packed f32x2 pairs (same 16B loads).
    ulonglong2 w[2][8];
#pragma unroll
    for (int r = 0; r < 2; r++) {
        const float* Wr = W + (size_t)(j0 + r) * DM;
#pragma unroll
        for (int c = 0; c < 8; c++)
            w[r][c] = *(const ulonglong2*)(Wr + c * 128 + lane * 4);
    }
    const float bias0 = bias[j0], bias1 = bias[j0 + 1];

    // ---- group 0: wait only for the first copy group ----
    asm volatile("cp.async.wait_group 1;" ::: "memory");
    __syncthreads();

#pragma unroll
    for (int g = 0; g < 2; g++) {
        const float* sa = s_act[g];
        unsigned long long a2[4][2];
#pragma unroll
        for (int b = 0; b < 4; b++) { a2[b][0] = 0ull; a2[b][1] = 0ull; }

#pragma unroll
        for (int c = 0; c < 8; c++) {
#pragma unroll
            for (int b = 0; b < 4; b++) {
                ulonglong2 x = *(const ulonglong2*)&sa[b * DM + c * 128 + lane * 4];
                ffma2(a2[b][0], x.x, w[0][c].x);   // rows 0: k even/odd pairs
                ffma2(a2[b][0], x.y, w[0][c].y);
                ffma2(a2[b][1], x.x, w[1][c].x);   // row 1
                ffma2(a2[b][1], x.y, w[1][c].y);
            }
        }

        // Unpack pairs -> 8 scalar chains, then one 5-level butterfly.
        float a[4][2];
#pragma unroll
        for (int b = 0; b < 4; b++) {
            a[b][0] = pair_sum(a2[b][0]);
            a[b][1] = pair_sum(a2[b][1]);
        }
#pragma unroll
        for (int off = 16; off; off >>= 1) {
#pragma unroll
            for (int b = 0; b < 4; b++) {
                a[b][0] += __shfl_xor_sync(0xffffffffu, a[b][0], off);
                a[b][1] += __shfl_xor_sync(0xffffffffu, a[b][1], off);
            }
        }

        if (lane == 0) {
            const int bb0 = b0 + g * 4;
#pragma unroll
            for (int b = 0; b < 4; b++) {
                out[(size_t)(bb0 + b) * DM + j0]     = (a[b][0] + bias0) * scale;
                out[(size_t)(bb0 + b) * DM + j0 + 1] = (a[b][1] + bias1) * scale;
            }
        }

        if (g == 0) {   // ---- group 1 arrival ----
            asm volatile("cp.async.wait_group 0;" ::: "memory");
            __syncthreads();
        }
    }
}

// ---------------------------------------------------------------------------
// Flash-decode attention over 4096 cached keys + 1 new token (R7-proven,
// at HBM roofline ~7.2 TB/s — UNCHANGED).
// One CTA per (b,h): 512 CTAs x 256 threads, single wave (4 CTAs/SM).
// float4 / half-warp layout; block-softmax over 4-key blocks per half.
// ---------------------------------------------------------------------------
__global__ void __launch_bounds__(256, 4)
attn_kernel(const float* __restrict__ Kc,
            const float* __restrict__ Vc)
{
    const int bh   = blockIdx.x;       // 0..511
    const int b    = bh >> 4;
    const int h    = bh & 15;
    const int warp = threadIdx.x >> 5;
    const int lane = threadIdx.x & 31;
    const int half = lane >> 4;        // 0 or 1
    const int li   = lane & 15;        // lane within half; dims 4*li..4*li+3

    __shared__ float4 sq[16];          // q, pre-scaled by 1/sqrt(DK)
    __shared__ float  sm[16], sl[16];
    __shared__ float4 so[16][16];

    if (threadIdx.x < 16)
        sq[threadIdx.x] = *(const float4*)(g_qp + b * DM + h * DK + 4 * threadIdx.x);
    __syncthreads();

    const float4 q4 = sq[li];

    const float* Kp = Kc + (size_t)bh * TC * DK + (size_t)half * DK + 4 * li;
    const float* Vp = Vc + (size_t)bh * TC * DK + (size_t)half * DK + 4 * li;

    float  m = -1e30f;
    float  l = 0.0f;
    float4 o = make_float4(0.f, 0.f, 0.f, 0.f);

    const int t0 = warp * (TC / 8);    // 512 keys per warp; 4/half per iter
    for (int t = t0; t < t0 + TC / 8; t += 8) {
        float4 kk[4], vv[4];
#pragma unroll
        for (int i = 0; i < 4; i++)
            kk[i] = __ldcs((const float4*)(Kp + (size_t)(t + 2 * i) * DK));
#pragma unroll
        for (int i = 0; i < 4; i++)
            vv[i] = __ldcs((const float4*)(Vp + (size_t)(t + 2 * i) * DK));

        float s[4];
#pragma unroll
        for (int i = 0; i < 4; i++)
            s[i] = kk[i].x * q4.x + kk[i].y * q4.y + kk[i].z * q4.z + kk[i].w * q4.w;
#pragma unroll
        for (int off = 8; off; off >>= 1)
#pragma unroll
            for (int i = 0; i < 4; i++)
                s[i] += __shfl_xor_sync(0xffffffffu, s[i], off);   // within half

        float bm = fmaxf(fmaxf(s[0], s[1]), fmaxf(s[2], s[3]));
        float mn = fmaxf(m, bm);

        float p[4];
#pragma unroll
        for (int i = 0; i < 4; i++) p[i] = __expf(s[i] - mn);

        float  lp = 0.0f;
        float4 op = make_float4(0.f, 0.f, 0.f, 0.f);
#pragma unroll
        for (int i = 0; i < 4; i++) {
            lp   += p[i];
            op.x += p[i] * vv[i].x;
            op.y += p[i] * vv[i].y;
            op.z += p[i] * vv[i].z;
            op.w += p[i] * vv[i].w;
        }

        float sc = __expf(m - mn);
        l   = l   * sc + lp;
        o.x = o.x * sc + op.x;
        o.y = o.y * sc + op.y;
        o.z = o.z * sc + op.z;
        o.w = o.w * sc + op.w;
        m   = mn;
    }

    // New (appended) token: warp 0 computes the score; half 0 folds it in.
    if (warp == 0) {
        float4 kk = *(const float4*)(g_kp + b * DM + h * DK + 4 * li);
        float4 vv = *(const float4*)(g_vp + b * DM + h * DK + 4 * li);
        float s = kk.x * q4.x + kk.y * q4.y + kk.z * q4.z + kk.w * q4.w;
#pragma unroll
        for (int off = 8; off; off >>= 1)
            s += __shfl_xor_sync(0xffffffffu, s, off);
        if (half == 0) {
            float mn = fmaxf(m, s);
            float sc = __expf(m - mn);
            float p  = __expf(s - mn);
            l   = l   * sc + p;
            o.x = o.x * sc + p * vv.x;
            o.y = o.y * sc + p * vv.y;
            o.z = o.z * sc + p * vv.z;
            o.w = o.w * sc + p * vv.w;
            m   = mn;
        }
    }

    const int idx = warp * 2 + half;   // 16 partial states
    if (li == 0) { sm[idx] = m; sl[idx] = l; }
    so[idx][li] = o;
    __syncthreads();

    // Combine 16 partial states; threads 0..63 each own one output dim.
    if (threadIdx.x < DK) {
        const int d = threadIdx.x;
        float M = sm[0];
#pragma unroll
        for (int i = 1; i < 16; i++) M = fmaxf(M, sm[i]);
        float L = 0.0f, O = 0.0f;
#pragma unroll
        for (int i = 0; i < 16; i++) {
            float e = __expf(sm[i] - M);
            L += e * sl[i];
            O += e * ((const float*)so[i])[d];
        }
        g_x[b * DM + h * DK + d] = O / L;
    }
}

// ---------------------------------------------------------------------------
// inputs (metadata order): 0 q, 1 key_pre, 2 value_pre,
//   3 wq, 4 bq, 5 wk, 6 bk, 7 wv, 8 bv, 9 wo, 10 bo
// output: [32, 1, 1024] fp32
// ---------------------------------------------------------------------------
extern "C" void kernel_launch(void* const* d_in, const int* in_sizes, int n_in,
                              void* d_out, int out_size)
{
    const float* q   = (const float*)d_in[0];
    const float* Kc  = (const float*)d_in[1];
    const float* Vc  = (const float*)d_in[2];
    const float* wq  = (const float*)d_in[3];
    const float* bq  = (const float*)d_in[4];
    const float* wk  = (const float*)d_in[5];
    const float* bk  = (const float*)d_in[6];
    const float* wv  = (const float*)d_in[7];
    const float* bv  = (const float*)d_in[8];
    const float* wo  = (const float*)d_in[9];
    const float* bo  = (const float*)d_in[10];
    float* out = (float*)d_out;

    const float qscale = 0.125f;  // 1/sqrt(DK)

    // QKV projections (grid.y selects matrix; q gets the softmax scale folded in)
    proj_kernel<<<dim3(DM / 8, 3, 4), 128>>>(0, q, wq, bq, wk, bk, wv, bv,
                                             nullptr, qscale);

    // Flash-decode attention over the cache + appended token (single wave)
    attn_kernel<<<BATCH * NH, 256>>>(Kc, Vc);

    // Output projection: reads g_x via device-side symbol, writes d_out
    proj_kernel<<<dim3(DM / 8, 1, 4), 128>>>(1, nullptr, wo, bo, nullptr, nullptr,
                                             nullptr, nullptr, out, 1.0f);
}